// round 17
// baseline (speedup 1.0000x reference)
#include <cuda_runtime.h>
#include <cuda_fp16.h>

// Problem constants
#define KSZ   15
#define PAD   10
#define L1    134
#define MQ    17956          // L1*L1 queries
#define NMEM  16384
#define KDIM  225
#define NC    67             // per-axis queries per parity class
#define MC    4489           // queries per class
#define KC    64             // compressed K (8x8 source window)
#define BPC   71             // M-tiles (of 64) per class
#define GEMM_BLOCKS (4*BPC)  // 284
#define GEMM_THREADS 192     // 6 warps: 2 (M) x 3 (j-thirds)
#define SLOT  8192           // bytes per B slice (64 rows x 128B, one split)
// smem: A tile (16KB) | 6 warps x 2 ring slots x 8KB
#define SM_A   0
#define SM_RING 16384
#define GEMM_SMEM (16384 + 6*2*SLOT)   // 114688 -> 2 CTAs/SM (3 warps/SMSP)

// -------- device scratch -----------------------------------------------------
__device__ __align__(16) unsigned char g_Ah[4 * BPC * 2 * SLOT];     // fp16 A
__device__ __align__(16) unsigned char g_Bh[4 * 256 * 2 * SLOT];     // fp16 B
__device__ __align__(16) float g_m2f[4 * NMEM * KC];  // fp32 compressed mem
__device__ __align__(16) float g_nhn[NMEM];           // negated half norms
__device__ __align__(16) int2 g_cand6[MQ * 3];        // top-2 per j-third
__device__ int   g_idx[MQ];
__device__ float g_raw[64 * 64];

// -------- helpers ------------------------------------------------------------
__device__ __forceinline__ void split2h(float v, unsigned short& h0,
                                        unsigned short& h1) {
    __half a = __float2half_rn(v);
    float r = v - __half2float(a);
    __half b = __float2half_rn(r);
    h0 = __half_as_ushort(a);
    h1 = __half_as_ushort(b);
}

__device__ __forceinline__ void mma16816(float& d0, float& d1, float& d2, float& d3,
                                         unsigned a0, unsigned a1, unsigned a2,
                                         unsigned a3, unsigned b0, unsigned b1) {
    asm volatile(
        "mma.sync.aligned.m16n8k16.row.col.f32.f16.f16.f32 "
        "{%0,%1,%2,%3},{%4,%5,%6,%7},{%8,%9},{%0,%1,%2,%3};"
        : "+f"(d0), "+f"(d1), "+f"(d2), "+f"(d3)
        : "r"(a0), "r"(a1), "r"(a2), "r"(a3), "r"(b0), "r"(b1));
}

__device__ __forceinline__ void cpa16(unsigned dst, const void* src) {
    asm volatile("cp.async.cg.shared.global [%0], [%1], 16;" :: "r"(dst), "l"(src));
}
__device__ __forceinline__ void cpa_commit() {
    asm volatile("cp.async.commit_group;" ::: "memory");
}
__device__ __forceinline__ void cpa_wait0() {
    asm volatile("cp.async.wait_group 0;" ::: "memory");
}
__device__ __forceinline__ void cpa_wait1() {
    asm volatile("cp.async.wait_group 1;" ::: "memory");
}

// rank-before: larger score first; ties -> lower index
__device__ __forceinline__ bool rank_gt(float a, int ia, float b, int ib) {
    return (a > b) || (a == b && ia < ib);
}

// ---------------------------------------------------------------------------
// slot sum (validated in R4); sq accumulates element squares (for norm fuse)
// ---------------------------------------------------------------------------
__device__ __forceinline__ float slotsum2(const float* __restrict__ row,
                                          int py, int px, int sy, int sx,
                                          float& sq) {
    int i0 = py ? 2 * sy - 1 : 2 * sy;
    int i1 = i0 + 1;
    int j0 = px ? 2 * sx - 1 : 2 * sx;
    int j1 = j0 + 1;
    float s = 0.f;
    if ((unsigned)i0 < 15u) {
        if ((unsigned)j0 < 15u) { float v = row[i0 * KSZ + j0]; s += v; sq += v * v; }
        if ((unsigned)j1 < 15u) { float v = row[i0 * KSZ + j1]; s += v; sq += v * v; }
    }
    if ((unsigned)i1 < 15u) {
        if ((unsigned)j0 < 15u) { float v = row[i1 * KSZ + j0]; s += v; sq += v * v; }
        if ((unsigned)j1 < 15u) { float v = row[i1 * KSZ + j1]; s += v; sq += v * v; }
    }
    return s;
}

// chunk-permuted in-row byte offset for logical k (0..63)
__device__ __forceinline__ int kpos(int row, int k) {
    int c = (k >> 1) & 3, h = (k >> 3) & 1, kk = k >> 4;
    int chunk = ((c * 2 + h + row) & 7);
    return chunk * 16 + kk * 4 + (k & 1) * 2;
}

// ---------------------------------------------------------------------------
// Prep B: compressed mem -> 2 fp16 splits in 64-row tiles; fused norms:
// cls==0 warps (32 lanes = one j) cover all 225 elements exactly once.
// ---------------------------------------------------------------------------
__global__ void prep_Bh(const float* __restrict__ mem) {
    int e = blockIdx.x * 256 + threadIdx.x;
    if (e >= 4 * NMEM * 32) return;
    int k2  = e & 31;
    int j   = (e >> 5) & (NMEM - 1);
    int cls = e >> 19;
    int py = cls >> 1, px = cls & 1;
    int s0 = 2 * k2, sy = s0 >> 3, sx = s0 & 7;
    const float* row = mem + j * KDIM;
    float sq = 0.f;
    float vx = slotsum2(row, py, px, sy, sx, sq);
    float vy = slotsum2(row, py, px, sy, sx + 1, sq);

    *(float2*)&g_m2f[((size_t)(cls * NMEM + j) << 6) + s0] = make_float2(vx, vy);

    if (cls == 0) {   // full-warp reduce of element squares -> norm
        #pragma unroll
        for (int o = 16; o; o >>= 1) sq += __shfl_down_sync(0xffffffffu, sq, o);
        if (k2 == 0) g_nhn[j] = -0.5f * sq;
    }

    unsigned short x0, x1, y0, y1;
    split2h(vx, x0, x1);
    split2h(vy, y0, y1);
    int r = j & 63;
    int off = kpos(r, s0);
    size_t base = ((size_t)(cls * 256 + (j >> 6)) * 2) * SLOT + (size_t)r * 128;
    ushort2 v0; v0.x = x0; v0.y = y0;
    ushort2 v1; v1.x = x1; v1.y = y1;
    *(ushort2*)(g_Bh + base + off) = v0;
    *(ushort2*)(g_Bh + base + SLOT + off) = v1;
}

// ---------------------------------------------------------------------------
// Prep A: compressed queries -> 2 fp16 splits in 64-row tiles
// ---------------------------------------------------------------------------
__global__ void prep_Ah(const float* __restrict__ image) {
    int e = blockIdx.x * 256 + threadIdx.x;
    if (e >= 4 * BPC * 64 * 32) return;
    int k2  = e & 31;
    int r   = (e >> 5) & 63;
    int r1  = e >> 11;                  // cls*BPC + tile
    int tile = r1 % BPC;
    int cls  = r1 / BPC;
    int py = cls >> 1, px = cls & 1;
    float vx = 0.f, vy = 0.f;
    int qc = tile * 64 + r;
    int s0 = 2 * k2, sy = s0 >> 3, sx = s0 & 7;
    if (qc < MC) {
        int a = qc / NC, b = qc - a * NC;
        int by = ((py + 2 * a) - PAD) >> 1;
        int bx = ((px + 2 * b) - PAD) >> 1;
        int yy = by + sy;
        if ((unsigned)yy < 64u) {
            int x0i = bx + sx, x1i = x0i + 1;
            if ((unsigned)x0i < 64u) vx = image[yy * 64 + x0i];
            if ((unsigned)x1i < 64u) vy = image[yy * 64 + x1i];
        }
    }
    unsigned short x0, x1, y0, y1;
    split2h(vx, x0, x1);
    split2h(vy, y0, y1);
    int off = kpos(r, s0);
    size_t base = (size_t)(r1 * 2) * SLOT + (size_t)r * 128;
    ushort2 v0; v0.x = x0; v0.y = y0;
    ushort2 v1; v1.x = x1; v1.y = y1;
    *(ushort2*)(g_Ah + base + off) = v0;
    *(ushort2*)(g_Ah + base + SLOT + off) = v1;
}

// ---------------------------------------------------------------------------
// Fused mma.sync GEMM + per-(query, j-third) top-2. BARRIER-FREE main loop.
// 284 blocks: (class, M-tile 64). 192 threads = 6 warps (wm in {0,1},
// jr in {0,1,2}); warp owns 32 rows x a ragged j-third (86/85/85 tiles of
// 64 j). Private 2-slot ring per warp, per-thread cp.async groups.
// 2 CTAs/SM -> 12 warps/SM = 3 per SMSP. A fragments reloaded per pass
// (register diet for the 170-reg cap); norms read in epilogue via __ldg.
// ---------------------------------------------------------------------------
__global__ void __launch_bounds__(GEMM_THREADS, 2) gemm_argmin() {
    extern __shared__ unsigned char smc[];
    unsigned sb = (unsigned)__cvta_generic_to_shared(smc);
    const int tid = threadIdx.x;
    const int wid = tid >> 5, lane = tid & 31;
    const int wm = wid & 1, jr = wid >> 1;           // jr in 0..2
    const int tu = lane >> 2, cfr = lane & 3;
    const int cls = blockIdx.x / BPC;
    const int tile_m = blockIdx.x - cls * BPC;

    const int ch0 = (cfr * 2 + 0 + tu) & 7;
    const int ch1 = (cfr * 2 + 1 + tu) & 7;

    const int NTW = 85 + (jr == 0);                  // 86,85,85 tiles
    const int TB  = (jr == 0) ? 0 : (86 + 85 * (jr - 1));  // 0,86,171

    // cooperative A tile load (16KB), the ONLY block barrier
    {
        const uint4* as =
            (const uint4*)(g_Ah + (size_t)((cls * BPC + tile_m) * 2) * SLOT);
        for (int i = tid; i < 1024; i += GEMM_THREADS)
            cpa16(sb + SM_A + i * 16, as + i);
        cpa_commit();
        cpa_wait0();
    }
    __syncthreads();

    const unsigned ringb = sb + SM_RING + wid * (2 * SLOT);
    const unsigned char* ringp = smc + SM_RING + wid * (2 * SLOT);
    const unsigned char* gBc =
        g_Bh + ((size_t)(cls * 256 + TB) * 2) * SLOT;

    // warp-private slice copy: 8KB, 16 cpa16 per lane, one commit group
    auto copy_slice = [&](int slotoff, const unsigned char* src) {
        unsigned dst = ringb + slotoff + lane * 16;
        const unsigned char* s = src + lane * 16;
        #pragma unroll
        for (int p = 0; p < 16; p++)
            cpa16(dst + p * 512, s + p * 512);
        cpa_commit();
    };

    // prime: slot0 = split0(tile0), slot1 = split1(tile0)
    copy_slice(0, gBc);
    copy_slice(SLOT, gBc + SLOT);

    const uint4* Ap0 = (const uint4*)(smc + SM_A);
    const uint4* Ap1 = (const uint4*)(smc + SM_A + SLOT);
    const int arow0 = (wm * 32 + 0 * 16) * 8;        // mt=0 base (+rr*8+tu rows)
    // rows: wm*32 + mt*16 + rr*8 + tu

    float rb1[4], rb2[4];
    int   ri1[4], ri2[4];
    #pragma unroll
    for (int x = 0; x < 4; x++) {
        rb1[x] = -3.4e38f; rb2[x] = -3.4e38f;
        ri1[x] = 0x7fffffff; ri2[x] = 0x7fffffff;
    }
    (void)arow0;

    for (int t = 0; t < NTW; t++) {
        cpa_wait1();                 // slot0 (split0 of tile t) ready

        float acc[2][8][4];
        #pragma unroll
        for (int mt = 0; mt < 2; mt++)
            #pragma unroll
            for (int nt = 0; nt < 8; nt++)
                #pragma unroll
                for (int q = 0; q < 4; q++) acc[mt][nt][q] = 0.f;

        const uint4* Bs0 = (const uint4*)ringp;
        const uint4* Bs1 = (const uint4*)(ringp + SLOT);

        // ---- pass 1: A0 * B0
        {
            uint4 af[2][2][2];
            #pragma unroll
            for (int mt = 0; mt < 2; mt++)
                #pragma unroll
                for (int rr = 0; rr < 2; rr++) {
                    int row = wm * 32 + mt * 16 + rr * 8 + tu;
                    af[mt][rr][0] = Ap0[row * 8 + ch0];
                    af[mt][rr][1] = Ap0[row * 8 + ch1];
                }
            #pragma unroll
            for (int ng = 0; ng < 2; ng++) {
                uint4 bp[4][2];
                #pragma unroll
                for (int i = 0; i < 4; i++) {
                    int n = (ng * 4 + i) * 8 + tu;
                    bp[i][0] = Bs0[n * 8 + ch0];
                    bp[i][1] = Bs0[n * 8 + ch1];
                }
                #pragma unroll
                for (int kk = 0; kk < 4; kk++)
                    #pragma unroll
                    for (int mt = 0; mt < 2; mt++) {
                        unsigned a0 = ((const unsigned*)&af[mt][0][0])[kk];
                        unsigned a1 = ((const unsigned*)&af[mt][1][0])[kk];
                        unsigned a2 = ((const unsigned*)&af[mt][0][1])[kk];
                        unsigned a3 = ((const unsigned*)&af[mt][1][1])[kk];
                        #pragma unroll
                        for (int i = 0; i < 4; i++) {
                            int nt = ng * 4 + i;
                            mma16816(acc[mt][nt][0], acc[mt][nt][1],
                                     acc[mt][nt][2], acc[mt][nt][3],
                                     a0, a1, a2, a3,
                                     ((const unsigned*)&bp[i][0])[kk],
                                     ((const unsigned*)&bp[i][1])[kk]);
                        }
                    }
            }
        }
        // ---- pass 2: A1 * B0
        {
            uint4 af[2][2][2];
            #pragma unroll
            for (int mt = 0; mt < 2; mt++)
                #pragma unroll
                for (int rr = 0; rr < 2; rr++) {
                    int row = wm * 32 + mt * 16 + rr * 8 + tu;
                    af[mt][rr][0] = Ap1[row * 8 + ch0];
                    af[mt][rr][1] = Ap1[row * 8 + ch1];
                }
            #pragma unroll
            for (int ng = 0; ng < 2; ng++) {
                uint4 bp[4][2];
                #pragma unroll
                for (int i = 0; i < 4; i++) {
                    int n = (ng * 4 + i) * 8 + tu;
                    bp[i][0] = Bs0[n * 8 + ch0];
                    bp[i][1] = Bs0[n * 8 + ch1];
                }
                #pragma unroll
                for (int kk = 0; kk < 4; kk++)
                    #pragma unroll
                    for (int mt = 0; mt < 2; mt++) {
                        unsigned a0 = ((const unsigned*)&af[mt][0][0])[kk];
                        unsigned a1 = ((const unsigned*)&af[mt][1][0])[kk];
                        unsigned a2 = ((const unsigned*)&af[mt][0][1])[kk];
                        unsigned a3 = ((const unsigned*)&af[mt][1][1])[kk];
                        #pragma unroll
                        for (int i = 0; i < 4; i++) {
                            int nt = ng * 4 + i;
                            mma16816(acc[mt][nt][0], acc[mt][nt][1],
                                     acc[mt][nt][2], acc[mt][nt][3],
                                     a0, a1, a2, a3,
                                     ((const unsigned*)&bp[i][0])[kk],
                                     ((const unsigned*)&bp[i][1])[kk]);
                        }
                    }
            }
        }

        // refill slot0 with split0 of tile t+1
        {
            int tn = (t + 1 < NTW) ? t + 1 : NTW - 1;
            copy_slice(0, gBc + (size_t)tn * 2 * SLOT);
        }

        cpa_wait1();                 // slot1 (split1 of tile t) ready

        // ---- pass 3: A0 * B1
        {
            uint4 af[2][2][2];
            #pragma unroll
            for (int mt = 0; mt < 2; mt++)
                #pragma unroll
                for (int rr = 0; rr < 2; rr++) {
                    int row = wm * 32 + mt * 16 + rr * 8 + tu;
                    af[mt][rr][0] = Ap0[row * 8 + ch0];
                    af[mt][rr][1] = Ap0[row * 8 + ch1];
                }
            #pragma unroll
            for (int ng = 0; ng < 2; ng++) {
                uint4 bp[4][2];
                #pragma unroll
                for (int i = 0; i < 4; i++) {
                    int n = (ng * 4 + i) * 8 + tu;
                    bp[i][0] = Bs1[n * 8 + ch0];
                    bp[i][1] = Bs1[n * 8 + ch1];
                }
                #pragma unroll
                for (int kk = 0; kk < 4; kk++)
                    #pragma unroll
                    for (int mt = 0; mt < 2; mt++) {
                        unsigned a0 = ((const unsigned*)&af[mt][0][0])[kk];
                        unsigned a1 = ((const unsigned*)&af[mt][1][0])[kk];
                        unsigned a2 = ((const unsigned*)&af[mt][0][1])[kk];
                        unsigned a3 = ((const unsigned*)&af[mt][1][1])[kk];
                        #pragma unroll
                        for (int i = 0; i < 4; i++) {
                            int nt = ng * 4 + i;
                            mma16816(acc[mt][nt][0], acc[mt][nt][1],
                                     acc[mt][nt][2], acc[mt][nt][3],
                                     a0, a1, a2, a3,
                                     ((const unsigned*)&bp[i][0])[kk],
                                     ((const unsigned*)&bp[i][1])[kk]);
                        }
                    }
            }
        }

        // refill slot1 with split1 of tile t+1
        {
            int tn = (t + 1 < NTW) ? t + 1 : NTW - 1;
            copy_slice(SLOT, gBc + (size_t)tn * 2 * SLOT + SLOT);
        }

        // ---- epilogue: score = dot + nhn (ldg); fmax tree; rare rescan
        int j0 = (TB + t) * 64;
        #pragma unroll
        for (int nt = 0; nt < 8; nt++) {
            float2 hn = __ldg((const float2*)&g_nhn[j0 + nt * 8 + cfr * 2]);
            #pragma unroll
            for (int mt = 0; mt < 2; mt++) {
                acc[mt][nt][0] += hn.x;
                acc[mt][nt][1] += hn.y;
                acc[mt][nt][2] += hn.x;
                acc[mt][nt][3] += hn.y;
            }
        }
        #pragma unroll
        for (int mt = 0; mt < 2; mt++)
            #pragma unroll
            for (int rr = 0; rr < 2; rr++) {
                int ctx = mt * 2 + rr;
                float sv[16];
                #pragma unroll
                for (int la = 0; la < 16; la++)
                    sv[la] = acc[mt][la >> 1][rr * 2 + (la & 1)];
                #pragma unroll
                for (int st = 8; st; st >>= 1)
                    #pragma unroll
                    for (int i = 0; i < st; i++)
                        sv[i] = fmaxf(sv[i], sv[i + st]);
                float mx = sv[0];
                if (mx > rb2[ctx]) {          // rare
                    int la = 0;
                    #pragma unroll
                    for (int i = 15; i >= 0; i--)
                        if (acc[mt][i >> 1][rr * 2 + (i & 1)] == mx) la = i;
                    int jarg = j0 + (la >> 1) * 8 + cfr * 2 + (la & 1);
                    if (mx > rb1[ctx]) {
                        rb2[ctx] = rb1[ctx]; ri2[ctx] = ri1[ctx];
                        rb1[ctx] = mx; ri1[ctx] = jarg;
                    } else { rb2[ctx] = mx; ri2[ctx] = jarg; }
                }
            }
    }

    // merge top-2 across the 4 lanes (cfr groups) sharing each row
    #pragma unroll
    for (int ctx = 0; ctx < 4; ctx++) {
        #pragma unroll
        for (int m = 1; m <= 2; m <<= 1) {
            float ob1 = __shfl_xor_sync(0xffffffffu, rb1[ctx], m);
            int   oi1 = __shfl_xor_sync(0xffffffffu, ri1[ctx], m);
            float ob2 = __shfl_xor_sync(0xffffffffu, rb2[ctx], m);
            int   oi2 = __shfl_xor_sync(0xffffffffu, ri2[ctx], m);
            if (rank_gt(ob1, oi1, rb1[ctx], ri1[ctx])) {
                if (rank_gt(rb1[ctx], ri1[ctx], ob2, oi2)) {
                    rb2[ctx] = rb1[ctx]; ri2[ctx] = ri1[ctx];
                } else { rb2[ctx] = ob2; ri2[ctx] = oi2; }
                rb1[ctx] = ob1; ri1[ctx] = oi1;
            } else if (rank_gt(ob1, oi1, rb2[ctx], ri2[ctx])) {
                rb2[ctx] = ob1; ri2[ctx] = oi1;
            }
        }
    }
    // each warp writes ITS j-third's top-2 into its own int2 slot
    if (cfr == 0) {
        #pragma unroll
        for (int ctx = 0; ctx < 4; ctx++) {
            int mt = ctx >> 1, rr = ctx & 1;
            int m_local = wm * 32 + mt * 16 + rr * 8 + tu;
            int qc = tile_m * 64 + m_local;
            if (qc < MC) {
                int py = cls >> 1, px = cls & 1;
                int a = qc / NC, b = qc - a * NC;
                int q = (py + 2 * a) * L1 + (px + 2 * b);
                int2 cd; cd.x = ri1[ctx]; cd.y = ri2[ctx];
                g_cand6[q * 3 + jr] = cd;
            }
        }
    }
}

// ---------------------------------------------------------------------------
// Repair: exact fp32 evaluation of the 6 candidates per query (top-2 from
// each j-third), score-max form; identical decisions to validated R4 path.
// ---------------------------------------------------------------------------
__global__ void repair(const float* __restrict__ image) {
    int q = blockIdx.x * 256 + threadIdx.x;
    if (q >= MQ) return;
    int2 c0 = g_cand6[q * 3 + 0];
    int2 c1 = g_cand6[q * 3 + 1];
    int2 c2 = g_cand6[q * 3 + 2];
    int cands[6] = {c0.x, c0.y, c1.x, c1.y, c2.x, c2.y};
    int r = q / L1, c = q - r * L1;
    int cls = (r & 1) * 2 + (c & 1);
    int by = (r - PAD) >> 1, bx = (c - PAD) >> 1;
    float x[KC];
    #pragma unroll
    for (int s = 0; s < KC; s++) {
        int sy = s >> 3, sx = s & 7;
        int yy = by + sy, xx = bx + sx;
        x[s] = ((unsigned)yy < 64u && (unsigned)xx < 64u)
                   ? image[yy * 64 + xx] : 0.f;
    }
    float best = -3.4e38f; int bi = 0x7fffffff;
    #pragma unroll
    for (int ci = 0; ci < 6; ci++) {
        int cj = cands[ci];
        const float* mm = g_m2f + ((size_t)(cls * NMEM + cj) << 6);
        float d = 0.f;
        #pragma unroll
        for (int s = 0; s < KC; s++) d += x[s] * mm[s];
        float sc = g_nhn[cj] + d;     // dot - 0.5|m|^2  (maximize)
        if (sc > best || (sc == best && cj < bi)) { best = sc; bi = cj; }
    }
    g_idx[q] = bi;
}

// ---------------------------------------------------------------------------
// Reconstruction: out_raw[a][b] = acc[2a+10][2b+10]
// ---------------------------------------------------------------------------
__global__ void recon(const float* __restrict__ mem) {
    int t = blockIdx.x * 256 + threadIdx.x;      // 0..4095
    if (t >= 4096) return;
    int a = t >> 6, b = t & 63;
    int y = 2 * a + PAD, x = 2 * b + PAD;
    float s = 0.f;
    #pragma unroll
    for (int i = 0; i < KSZ; i++) {
        int ry = y - i;
        if ((unsigned)ry >= (unsigned)L1) continue;
        int rowbase = ry * L1;
        #pragma unroll
        for (int j = 0; j < KSZ; j++) {
            int rx = x - j;
            if ((unsigned)rx >= (unsigned)L1) continue;
            s += mem[g_idx[rowbase + rx] * KDIM + i * KSZ + j];
        }
    }
    g_raw[t] = s;
}

// max-normalize (single block)
__global__ void normalize_out(float* __restrict__ out) {
    __shared__ float smx[256];
    int tid = threadIdx.x;
    float mx = -3.4e38f;
    for (int i = tid; i < 4096; i += 256) mx = fmaxf(mx, g_raw[i]);
    smx[tid] = mx;
    __syncthreads();
    for (int o = 128; o; o >>= 1) {
        if (tid < o) smx[tid] = fmaxf(smx[tid], smx[tid + o]);
        __syncthreads();
    }
    float m = smx[0];
    for (int i = tid; i < 4096; i += 256) out[i] = g_raw[i] / m;
}

// ---------------------------------------------------------------------------
extern "C" void kernel_launch(void* const* d_in, const int* in_sizes, int n_in,
                              void* d_out, int out_size) {
    const float* image = (const float*)d_in[0];   // 64*64
    const float* mem   = (const float*)d_in[1];   // 16384*225
    float* out = (float*)d_out;                   // 64*64

    cudaFuncSetAttribute(gemm_argmin,
                         cudaFuncAttributeMaxDynamicSharedMemorySize,
                         GEMM_SMEM);

    {
        int n = 4 * BPC * 64 * 32;
        prep_Ah<<<(n + 255) / 256, 256>>>(image);
    }
    {
        int n = 4 * NMEM * 32;
        prep_Bh<<<(n + 255) / 256, 256>>>(mem);   // norms fused in
    }

    gemm_argmin<<<GEMM_BLOCKS, GEMM_THREADS, GEMM_SMEM>>>();

    repair<<<(MQ + 255) / 256, 256>>>(image);
    recon<<<16, 256>>>(mem);
    normalize_out<<<1, 256>>>(out);
}